// round 6
// baseline (speedup 1.0000x reference)
#include <cuda_runtime.h>
#include <math_constants.h>

// Regular (3,6) LDPC neural offset min-sum decoder.
// edge_var = repeat(arange(NVAR),3) -> edges of var v are {3v,3v+1,3v+2}:
// the variable side needs NO indirection and is fully vectorizable (float4).
// Only the check side (edge_chk = random permutation) requires gather/scatter:
// 2 random 32B L2 wavefronts per edge per iteration (irreducible crossing).
//
// Tie semantics: reference's first-index argmin + min2 is value-equivalent to
// plain two-smallest tracking (ties => min2==min1 => identical raw on all
// edges), so the atomic-order-nondeterministic check edge table still yields
// bit-deterministic output. Per-variable arithmetic order kept identical to
// the previous kernel (rel_err was exactly 0.0).

#define NVAR  524288
#define NCHK  262144
#define NEDGE 1572864
#define DCC   6

static __device__ float g_v2c[NEDGE];
static __device__ float g_c2v[NEDGE];
static __device__ int   g_ce[NEDGE];    // check-major list of edge ids
static __device__ int   g_cnt[NCHK];    // per-check fill counters

// One thread handles 4 variables: writes v2c[12v..12v+11] (3x float4) and
// zeroes 2 check counters (int2). 131072 threads.
__global__ void k_init(const float* __restrict__ llr) {
    int i = blockIdx.x * blockDim.x + threadIdx.x;   // i in [0, NVAR/4)
    if (i >= NVAR / 4) return;

    // zero counters: NCHK/ (NVAR/4) = 2 per thread
    ((int2*)g_cnt)[i] = make_int2(0, 0);

    float4 l = ((const float4*)llr)[i];
    float4* dst = (float4*)(g_v2c + 12 * i);
    dst[0] = make_float4(l.x, l.x, l.x, l.y);
    dst[1] = make_float4(l.y, l.y, l.z, l.z);
    dst[2] = make_float4(l.z, l.w, l.w, l.w);
}

// 4 edges per thread via int4 read.
__global__ void k_build(const int* __restrict__ edge_chk) {
    int i = blockIdx.x * blockDim.x + threadIdx.x;   // i in [0, NEDGE/4)
    if (i >= NEDGE / 4) return;
    int4 c4 = ((const int4*)edge_chk)[i];
    int e = 4 * i;
    int s;
    s = atomicAdd(&g_cnt[c4.x], 1); g_ce[c4.x * DCC + s] = e + 0;
    s = atomicAdd(&g_cnt[c4.y], 1); g_ce[c4.y * DCC + s] = e + 1;
    s = atomicAdd(&g_cnt[c4.z], 1); g_ce[c4.z * DCC + s] = e + 2;
    s = atomicAdd(&g_cnt[c4.w], 1); g_ce[c4.w * DCC + s] = e + 3;
}

__global__ void k_check(const float* __restrict__ beta,
                        const float* __restrict__ alpha, int t) {
    int c = blockIdx.x * blockDim.x + threadIdx.x;
    if (c >= NCHK) return;

    // edge table: 24B per check, 8B aligned -> 3x int2
    const int2* ep = (const int2*)(g_ce + c * DCC);
    int2 e01 = ep[0];
    int2 e23 = ep[1];
    int2 e45 = ep[2];
    int e[DCC] = {e01.x, e01.y, e23.x, e23.y, e45.x, e45.y};

    float v[DCC];
#pragma unroll
    for (int s = 0; s < DCC; s++) v[s] = g_v2c[e[s]];   // 6 random L2 gathers

    float m1 = CUDART_INF_F, m2 = CUDART_INF_F, sp = 1.0f;
    int   as = 0;
    float sg[DCC];
#pragma unroll
    for (int s = 0; s < DCC; s++) {
        float x = v[s];
        float g = (x > 0.0f) ? 1.0f : ((x < 0.0f) ? -1.0f : 0.0f); // jnp.sign
        sg[s] = g;
        sp *= g;
        float m = fabsf(x);
        if (m < m1) { m2 = m1; m1 = m; as = s; }
        else if (m < m2) { m2 = m; }
    }

    float b = __ldg(&beta[t]);
    float a = __ldg(&alpha[t]);
    float r1 = fmaxf(m1 - b, 0.0f) - a;
    float r2 = fmaxf(m2 - b, 0.0f) - a;

#pragma unroll
    for (int s = 0; s < DCC; s++) {
        float val = (s == as) ? r2 : r1;
        g_c2v[e[s]] = sp * sg[s] * val;                 // 6 random L2 scatters
    }
}

// 4 variables per thread, all 128-bit memory ops.
__global__ void k_var(const float* __restrict__ llr) {
    int i = blockIdx.x * blockDim.x + threadIdx.x;   // i in [0, NVAR/4)
    if (i >= NVAR / 4) return;

    const float4* src = (const float4*)(g_c2v + 12 * i);
    float4 a = src[0];   // v0: a.x a.y a.z | v1: a.w ...
    float4 b = src[1];
    float4 d = src[2];
    float4 l = ((const float4*)llr)[i];

    float p0 = l.x + (a.x + a.y + a.z);
    float p1 = l.y + (a.w + b.x + b.y);
    float p2 = l.z + (b.z + b.w + d.x);
    float p3 = l.w + (d.y + d.z + d.w);

    float4* dst = (float4*)(g_v2c + 12 * i);
    dst[0] = make_float4(p0 - a.x, p0 - a.y, p0 - a.z, p1 - a.w);
    dst[1] = make_float4(p1 - b.x, p1 - b.y, p2 - b.z, p2 - b.w);
    dst[2] = make_float4(p2 - d.x, p3 - d.y, p3 - d.z, p3 - d.w);
}

// Final: out[0..NVAR) = bits (0/1 float), out[NVAR..2NVAR) = posterior.
__global__ void k_final_f(const float* __restrict__ llr, float* __restrict__ out) {
    int i = blockIdx.x * blockDim.x + threadIdx.x;
    if (i >= NVAR / 4) return;

    const float4* src = (const float4*)(g_c2v + 12 * i);
    float4 a = src[0];
    float4 b = src[1];
    float4 d = src[2];
    float4 l = ((const float4*)llr)[i];

    float p0 = l.x + (a.x + a.y + a.z);
    float p1 = l.y + (a.w + b.x + b.y);
    float p2 = l.z + (b.z + b.w + d.x);
    float p3 = l.w + (d.y + d.z + d.w);

    ((float4*)out)[i] = make_float4(p0 < 0.0f ? 1.0f : 0.0f,
                                    p1 < 0.0f ? 1.0f : 0.0f,
                                    p2 < 0.0f ? 1.0f : 0.0f,
                                    p3 < 0.0f ? 1.0f : 0.0f);
    ((float4*)(out + NVAR))[i] = make_float4(p0, p1, p2, p3);
}

__global__ void k_final_i(const float* __restrict__ llr, int* __restrict__ out) {
    int i = blockIdx.x * blockDim.x + threadIdx.x;
    if (i >= NVAR / 4) return;

    const float4* src = (const float4*)(g_c2v + 12 * i);
    float4 a = src[0];
    float4 b = src[1];
    float4 d = src[2];
    float4 l = ((const float4*)llr)[i];

    float p0 = l.x + (a.x + a.y + a.z);
    float p1 = l.y + (a.w + b.x + b.y);
    float p2 = l.z + (b.z + b.w + d.x);
    float p3 = l.w + (d.y + d.z + d.w);

    ((int4*)out)[i] = make_int4(p0 < 0.0f ? 1 : 0, p1 < 0.0f ? 1 : 0,
                                p2 < 0.0f ? 1 : 0, p3 < 0.0f ? 1 : 0);
}

extern "C" void kernel_launch(void* const* d_in, const int* in_sizes, int n_in,
                              void* d_out, int out_size) {
    const float* llr      = (const float*)d_in[0];
    const float* beta     = (const float*)d_in[1];
    const float* alpha    = (const float*)d_in[2];
    // d_in[3] = edge_var (implicit: e/3, unused), d_in[4] = edge_chk
    const int*   edge_chk = (const int*)d_in[4];
    const int T = in_sizes[1];   // number of iterations (10)

    const int TB = 256;
    const int gV4 = (NVAR / 4 + TB - 1) / TB;    // 512 blocks
    const int gE4 = (NEDGE / 4 + TB - 1) / TB;   // 1536 blocks
    const int gC  = (NCHK + TB - 1) / TB;        // 1024 blocks

    k_init <<<gV4, TB>>>(llr);
    k_build<<<gE4, TB>>>(edge_chk);

    for (int t = 0; t < T; t++) {
        k_check<<<gC, TB>>>(beta, alpha, t);
        if (t < T - 1) k_var<<<gV4, TB>>>(llr);
    }

    if (out_size >= 2 * NVAR) {
        k_final_f<<<gV4, TB>>>(llr, (float*)d_out);
    } else {
        k_final_i<<<gV4, TB>>>(llr, (int*)d_out);
    }
}

// round 12
// speedup vs baseline: 1.1259x; 1.1259x over previous
#include <cuda_runtime.h>
#include <math_constants.h>

// Regular (3,6) LDPC neural offset min-sum decoder — single-kernel-per-iteration,
// deterministic (no atomics in the iteration path).
//
// Variable state is packed per-variable into one float4:
//     buf[v] = { c2v(edge 3v), c2v(3v+1), c2v(3v+2), llr[v] }
// ping-ponged between two buffers. The check kernel per edge does ONE random
// 16B read (one 32B L2 sector, same cost as a 4B read) which yields both the
// posterior p = llr + ((c0+c1)+c2) (computed in the exact FP order that scored
// rel_err 0.0 in the 2-kernel version) and the subtrahend c_slot, giving
// v2c = p - c_slot bitwise-identical to the reference. New c2v messages go
// back with one random 4B store into buf_next[v] (unique writer per slot,
// no atomics -> fully deterministic). The per-iteration variable kernel is
// thus eliminated entirely: T+3 launches total.
//
// Check-side tie semantics: duplicate minima => min2==min1 => identical raw on
// every edge, so the atomic-order-nondeterministic build table is harmless
// (verified rel_err 0.0 previously). jnp.sign(0)=0 preserved.

#define NVAR  524288
#define NCHK  262144
#define NEDGE 1572864
#define DCC   6

static __device__ float4 g_buf[2][NVAR];   // {c2v0, c2v1, c2v2, llr}
static __device__ int    g_ct[NEDGE];      // per check-major slot: 4*v + slot
static __device__ int    g_cnt[NCHK];      // per-check fill counters

// One thread per 4 variables: buf[0]=buf[1]={0,0,0,llr}, zero counters.
__global__ void k_init(const float* __restrict__ llr) {
    int i = blockIdx.x * blockDim.x + threadIdx.x;   // [0, NVAR/4)
    if (i >= NVAR / 4) return;

    float4 l = ((const float4*)llr)[i];
    float4 b0 = make_float4(0.f, 0.f, 0.f, l.x);
    float4 b1 = make_float4(0.f, 0.f, 0.f, l.y);
    float4 b2 = make_float4(0.f, 0.f, 0.f, l.z);
    float4 b3 = make_float4(0.f, 0.f, 0.f, l.w);
    g_buf[0][4 * i + 0] = b0;  g_buf[1][4 * i + 0] = b0;
    g_buf[0][4 * i + 1] = b1;  g_buf[1][4 * i + 1] = b1;
    g_buf[0][4 * i + 2] = b2;  g_buf[1][4 * i + 2] = b2;
    g_buf[0][4 * i + 3] = b3;  g_buf[1][4 * i + 3] = b3;

    if (i < NCHK / 4) ((int4*)g_cnt)[i] = make_int4(0, 0, 0, 0);
}

// 4 edges per thread: fill check-major table with pack = 4*(e/3) + (e%3) = e + e/3.
__global__ void k_build(const int* __restrict__ edge_chk) {
    int i = blockIdx.x * blockDim.x + threadIdx.x;   // [0, NEDGE/4)
    if (i >= NEDGE / 4) return;
    int4 c4 = ((const int4*)edge_chk)[i];
    int e = 4 * i;
    int s;
    s = atomicAdd(&g_cnt[c4.x], 1); g_ct[c4.x * DCC + s] = (e + 0) + (e + 0) / 3;
    s = atomicAdd(&g_cnt[c4.y], 1); g_ct[c4.y * DCC + s] = (e + 1) + (e + 1) / 3;
    s = atomicAdd(&g_cnt[c4.z], 1); g_ct[c4.z * DCC + s] = (e + 2) + (e + 2) / 3;
    s = atomicAdd(&g_cnt[c4.w], 1); g_ct[c4.w * DCC + s] = (e + 3) + (e + 3) / 3;
}

// One thread per check. cur/nxt select the ping-pong buffers.
__global__ void k_check(const float* __restrict__ beta,
                        const float* __restrict__ alpha, int t) {
    int c = blockIdx.x * blockDim.x + threadIdx.x;
    if (c >= NCHK) return;

    int cur = t & 1;
    const float4* __restrict__ bin  = g_buf[cur];
    float*        __restrict__ bout = (float*)g_buf[cur ^ 1];

    // table: 24B @ 8B alignment -> 3x int2, coalesced
    const int2* tp = (const int2*)(g_ct + c * DCC);
    int2 t01 = tp[0], t23 = tp[1], t45 = tp[2];
    int pk[DCC] = {t01.x, t01.y, t23.x, t23.y, t45.x, t45.y};

    // 6 random 16B gathers, issued back-to-back for MLP
    float4 f[DCC];
#pragma unroll
    for (int s = 0; s < DCC; s++) f[s] = __ldg(&bin[pk[s] >> 2]);

    float m1 = CUDART_INF_F, m2 = CUDART_INF_F, sp = 1.0f;
    int   as = 0;
    float sg[DCC];
#pragma unroll
    for (int s = 0; s < DCC; s++) {
        int slot = pk[s] & 3;
        float4 q = f[s];
        float c_old = (slot == 0) ? q.x : ((slot == 1) ? q.y : q.z);
        float p = q.w + ((q.x + q.y) + q.z);   // exact order: rel_err 0.0 form
        float x = p - c_old;                   // v2c
        float g = (x > 0.0f) ? 1.0f : ((x < 0.0f) ? -1.0f : 0.0f); // jnp.sign
        sg[s] = g;
        sp *= g;
        float m = fabsf(x);
        if (m < m1) { m2 = m1; m1 = m; as = s; }
        else if (m < m2) { m2 = m; }
    }

    float b = __ldg(&beta[t]);
    float a = __ldg(&alpha[t]);
    float r1 = fmaxf(m1 - b, 0.0f) - a;
    float r2 = fmaxf(m2 - b, 0.0f) - a;

    // 6 random 4B scatters; bout is float-aliased so addr = bout + pack
#pragma unroll
    for (int s = 0; s < DCC; s++) {
        float val = sp * sg[s] * ((s == as) ? r2 : r1);
        bout[pk[s]] = val;
    }
}

// Final: posterior from buf[T&1], coalesced. out layout [bits | posterior].
__global__ void k_final_f(float* __restrict__ out, int T) {
    int v = blockIdx.x * blockDim.x + threadIdx.x;
    if (v >= NVAR) return;
    float4 q = g_buf[T & 1][v];
    float p = q.w + ((q.x + q.y) + q.z);
    out[v]        = (p < 0.0f) ? 1.0f : 0.0f;
    out[NVAR + v] = p;
}

__global__ void k_final_i(int* __restrict__ out, int T) {
    int v = blockIdx.x * blockDim.x + threadIdx.x;
    if (v >= NVAR) return;
    float4 q = g_buf[T & 1][v];
    float p = q.w + ((q.x + q.y) + q.z);
    out[v] = (p < 0.0f) ? 1 : 0;
}

extern "C" void kernel_launch(void* const* d_in, const int* in_sizes, int n_in,
                              void* d_out, int out_size) {
    const float* llr      = (const float*)d_in[0];
    const float* beta     = (const float*)d_in[1];
    const float* alpha    = (const float*)d_in[2];
    // d_in[3] = edge_var (implicit e/3, unused), d_in[4] = edge_chk
    const int*   edge_chk = (const int*)d_in[4];
    const int T = in_sizes[1];   // 10

    const int TB  = 256;
    const int gV4 = (NVAR / 4 + TB - 1) / TB;    // 512
    const int gE4 = (NEDGE / 4 + TB - 1) / TB;   // 1536
    const int gC  = (NCHK + TB - 1) / TB;        // 1024
    const int gV  = (NVAR + TB - 1) / TB;        // 2048

    k_init <<<gV4, TB>>>(llr);
    k_build<<<gE4, TB>>>(edge_chk);

    for (int t = 0; t < T; t++)
        k_check<<<gC, TB>>>(beta, alpha, t);

    if (out_size >= 2 * NVAR) {
        k_final_f<<<gV, TB>>>((float*)d_out, T);
    } else {
        k_final_i<<<gV, TB>>>((int*)d_out, T);
    }
}